// round 1
// baseline (speedup 1.0000x reference)
#include <cuda_runtime.h>
#include <cuda_bf16.h>
#include <cstdint>

// Problem constants (fixed problem)
#define BATCH 32
#define TT    4096
#define HH    256
#define TB    (TT * BATCH)   // 131072 rows

// Scratch (static device arrays: allowed; no cudaMalloc)
__device__ float g_pre1[BATCH * HH];       // 32 KB
__device__ float g_w2t[HH * HH];           // W2^T, k-major: g_w2t[k*256 + h], 256 KB
__device__ float g_scores[BATCH * TT];     // transposed scores [b][t], 512 KB

// ---------------------------------------------------------------------------
// helpers: packed f32x2 FMA (FFMA2), cp.async
// ---------------------------------------------------------------------------
__device__ __forceinline__ unsigned long long dupf(float x) {
    unsigned long long r;
    asm("mov.b64 %0, {%1, %1};" : "=l"(r) : "f"(x));
    return r;
}
__device__ __forceinline__ float2 unpk(unsigned long long a) {
    float2 f;
    asm("mov.b64 {%0, %1}, %2;" : "=f"(f.x), "=f"(f.y) : "l"(a));
    return f;
}
#define FFMA2(c, a, b) asm("fma.rn.f32x2 %0, %1, %2, %0;" : "+l"(c) : "l"(a), "l"(b))

__device__ __forceinline__ void cp16_cg(void* smem_dst, const void* gsrc) {
    unsigned s = (unsigned)__cvta_generic_to_shared(smem_dst);
    asm volatile("cp.async.cg.shared.global [%0], [%1], 16;\n" :: "r"(s), "l"(gsrc));
}
__device__ __forceinline__ void cp16_ca(void* smem_dst, const void* gsrc) {
    unsigned s = (unsigned)__cvta_generic_to_shared(smem_dst);
    asm volatile("cp.async.ca.shared.global [%0], [%1], 16;\n" :: "r"(s), "l"(gsrc));
}
__device__ __forceinline__ void cp_commit() {
    asm volatile("cp.async.commit_group;\n" ::: "memory");
}
__device__ __forceinline__ void cp_wait1() {
    asm volatile("cp.async.wait_group 1;\n" ::: "memory");
}
__device__ __forceinline__ void cp_wait0() {
    asm volatile("cp.async.wait_group 0;\n" ::: "memory");
}

// ---------------------------------------------------------------------------
// Kernel 1: pre1[b,h] = sum_k W1[h,k] * hidden[b,k] + bias[h]
// One warp per (b,h). Grid: 1024 blocks x 256 threads = 8192 warps.
// ---------------------------------------------------------------------------
__global__ void pre1_kernel(const float* __restrict__ hidden,
                            const float* __restrict__ attn_w,
                            const float* __restrict__ attn_b) {
    int gw   = (blockIdx.x * blockDim.x + threadIdx.x) >> 5;   // 0..8191
    int lane = threadIdx.x & 31;
    int b = gw >> 8;
    int h = gw & 255;
    const float4* hp = (const float4*)(hidden + (size_t)b * HH);
    const float4* wp = (const float4*)(attn_w + (size_t)h * (2 * HH));
    float4 x0 = hp[lane],     w0 = wp[lane];
    float4 x1 = hp[lane + 32], w1 = wp[lane + 32];
    float s = x0.x * w0.x + x0.y * w0.y + x0.z * w0.z + x0.w * w0.w
            + x1.x * w1.x + x1.y * w1.y + x1.z * w1.z + x1.w * w1.w;
    #pragma unroll
    for (int o = 16; o; o >>= 1) s += __shfl_xor_sync(0xffffffffu, s, o);
    if (lane == 0) g_pre1[gw] = s + attn_b[h];
}

// ---------------------------------------------------------------------------
// Kernel 2: transpose W2 -> g_w2t[k][h]  (W2[h,k] = attn_w[h*512 + 256 + k])
// ---------------------------------------------------------------------------
__global__ void w2t_kernel(const float* __restrict__ attn_w) {
    int k = blockIdx.x;
    int h = threadIdx.x;
    g_w2t[k * HH + h] = attn_w[(size_t)h * (2 * HH) + HH + k];
}

// ---------------------------------------------------------------------------
// Kernel 3: fused GEMM + relu + v-dot.
//   C[r, h] = sum_k enc[r, k] * W2t[k, h]
//   scores[b(r), t(r)] = sum_h v[h] * relu(C[r,h] + pre1[b(r), h])
// CTA: 64 rows x 256 cols. 256 threads (tx 16 x ty 16): 4 rows x 16 cols each.
// Double-buffered cp.async, inner loop = packed f32x2 FMA.
// ---------------------------------------------------------------------------
#define BM 64
#define BK 32
#define A_PITCH 36   // padded row pitch for A tile
#define SMEM_ENERGY ((2*BM*A_PITCH + 2*BK*HH) * 4)   // 83968 bytes

__global__ __launch_bounds__(256, 2)
void energy_kernel(const float* __restrict__ enc,
                   const float* __restrict__ v) {
    extern __shared__ float smem[];
    float* Ast = smem;                      // [2][BM][A_PITCH]  row-major, padded
    float* Bsm = smem + 2 * BM * A_PITCH;   // [2][BK][HH]       k-major

    const int tid = threadIdx.x;
    const int tx = tid & 15, ty = tid >> 4;
    const int r0 = blockIdx.x * BM;

    unsigned long long acc[4][8];
    #pragma unroll
    for (int i = 0; i < 4; i++)
        #pragma unroll
        for (int j = 0; j < 8; j++) acc[i][j] = 0ull;

    // --- stage loader ---
    auto load_stage = [&](int buf, int kc) {
        // A tile: 64 rows x 32 k-floats = 512 float4 chunks; 2 per thread
        #pragma unroll
        for (int l = 0; l < 2; l++) {
            int idx = tid + l * 256;          // 0..511
            int row = idx >> 3;
            int k4  = (idx & 7) * 4;
            cp16_cg(&Ast[buf * (BM * A_PITCH) + row * A_PITCH + k4],
                    enc + (size_t)(r0 + row) * HH + kc + k4);
        }
        // B tile: 32 k x 256 h = 2048 float4 chunks; 8 per thread
        #pragma unroll
        for (int l = 0; l < 8; l++) {
            int idx = tid + l * 256;          // 0..2047
            int k   = idx >> 6;
            int h4  = (idx & 63) * 4;
            cp16_ca(&Bsm[buf * (BK * HH) + k * HH + h4],
                    g_w2t + (size_t)(kc + k) * HH + h4);
        }
    };

    load_stage(0, 0);
    cp_commit();

    for (int s = 0; s < 8; ++s) {
        if (s < 7) { load_stage((s + 1) & 1, (s + 1) * BK); cp_commit(); }
        if (s < 7) cp_wait1(); else cp_wait0();
        __syncthreads();

        const int buf = s & 1;
        const float* A = Ast + buf * (BM * A_PITCH);
        const float* B = Bsm + buf * (BK * HH);

        #pragma unroll 8
        for (int k = 0; k < BK; k++) {
            float a0 = A[(ty * 4 + 0) * A_PITCH + k];
            float a1 = A[(ty * 4 + 1) * A_PITCH + k];
            float a2 = A[(ty * 4 + 2) * A_PITCH + k];
            float a3 = A[(ty * 4 + 3) * A_PITCH + k];
            ulonglong2 B0 = *(const ulonglong2*)&B[k * HH +   0 + tx * 4];
            ulonglong2 B1 = *(const ulonglong2*)&B[k * HH +  64 + tx * 4];
            ulonglong2 B2 = *(const ulonglong2*)&B[k * HH + 128 + tx * 4];
            ulonglong2 B3 = *(const ulonglong2*)&B[k * HH + 192 + tx * 4];
            unsigned long long d0 = dupf(a0), d1 = dupf(a1), d2 = dupf(a2), d3 = dupf(a3);

            FFMA2(acc[0][0], d0, B0.x); FFMA2(acc[0][1], d0, B0.y);
            FFMA2(acc[0][2], d0, B1.x); FFMA2(acc[0][3], d0, B1.y);
            FFMA2(acc[0][4], d0, B2.x); FFMA2(acc[0][5], d0, B2.y);
            FFMA2(acc[0][6], d0, B3.x); FFMA2(acc[0][7], d0, B3.y);

            FFMA2(acc[1][0], d1, B0.x); FFMA2(acc[1][1], d1, B0.y);
            FFMA2(acc[1][2], d1, B1.x); FFMA2(acc[1][3], d1, B1.y);
            FFMA2(acc[1][4], d1, B2.x); FFMA2(acc[1][5], d1, B2.y);
            FFMA2(acc[1][6], d1, B3.x); FFMA2(acc[1][7], d1, B3.y);

            FFMA2(acc[2][0], d2, B0.x); FFMA2(acc[2][1], d2, B0.y);
            FFMA2(acc[2][2], d2, B1.x); FFMA2(acc[2][3], d2, B1.y);
            FFMA2(acc[2][4], d2, B2.x); FFMA2(acc[2][5], d2, B2.y);
            FFMA2(acc[2][6], d2, B3.x); FFMA2(acc[2][7], d2, B3.y);

            FFMA2(acc[3][0], d3, B0.x); FFMA2(acc[3][1], d3, B0.y);
            FFMA2(acc[3][2], d3, B1.x); FFMA2(acc[3][3], d3, B1.y);
            FFMA2(acc[3][4], d3, B2.x); FFMA2(acc[3][5], d3, B2.y);
            FFMA2(acc[3][6], d3, B3.x); FFMA2(acc[3][7], d3, B3.y);
        }
        __syncthreads();
    }

    // Epilogue: + pre1, relu, dot with v, reduce across tx, store transposed
    #pragma unroll
    for (int i = 0; i < 4; i++) {
        int row = ty * 4 + i;
        int r   = r0 + row;
        int bb  = r & 31;             // batch index
        const float* p1 = g_pre1 + bb * HH;
        float ssum = 0.f;
        #pragma unroll
        for (int jj = 0; jj < 4; jj++) {
            int h = jj * 64 + tx * 4;
            float2 c0 = unpk(acc[i][2 * jj + 0]);
            float2 c1 = unpk(acc[i][2 * jj + 1]);
            float e;
            e = c0.x + __ldg(&p1[h + 0]); ssum += fmaxf(e, 0.f) * __ldg(&v[h + 0]);
            e = c0.y + __ldg(&p1[h + 1]); ssum += fmaxf(e, 0.f) * __ldg(&v[h + 1]);
            e = c1.x + __ldg(&p1[h + 2]); ssum += fmaxf(e, 0.f) * __ldg(&v[h + 2]);
            e = c1.y + __ldg(&p1[h + 3]); ssum += fmaxf(e, 0.f) * __ldg(&v[h + 3]);
        }
        #pragma unroll
        for (int o = 8; o; o >>= 1) ssum += __shfl_xor_sync(0xffffffffu, ssum, o);
        if (tx == 0) g_scores[(r & 31) * TT + (r >> 5)] = ssum;  // [b][t]
    }
}

// ---------------------------------------------------------------------------
// Kernel 4: softmax over T per batch row. One CTA (1024 thr) per b.
// ---------------------------------------------------------------------------
__global__ void softmax_kernel(float* __restrict__ out) {
    int b = blockIdx.x, tid = threadIdx.x;
    __shared__ float red[32];
    __shared__ float bc;
    const float* sc = g_scores + (size_t)b * TT;

    float x0 = sc[tid], x1 = sc[tid + 1024], x2 = sc[tid + 2048], x3 = sc[tid + 3072];
    float m = fmaxf(fmaxf(x0, x1), fmaxf(x2, x3));
    #pragma unroll
    for (int o = 16; o; o >>= 1) m = fmaxf(m, __shfl_xor_sync(0xffffffffu, m, o));
    if ((tid & 31) == 0) red[tid >> 5] = m;
    __syncthreads();
    if (tid < 32) {
        float t = red[tid];
        #pragma unroll
        for (int o = 16; o; o >>= 1) t = fmaxf(t, __shfl_xor_sync(0xffffffffu, t, o));
        if (tid == 0) bc = t;
    }
    __syncthreads();
    m = bc;
    float e0 = expf(x0 - m), e1 = expf(x1 - m), e2 = expf(x2 - m), e3 = expf(x3 - m);
    float ssum = e0 + e1 + e2 + e3;
    #pragma unroll
    for (int o = 16; o; o >>= 1) ssum += __shfl_xor_sync(0xffffffffu, ssum, o);
    if ((tid & 31) == 0) red[tid >> 5] = ssum;
    __syncthreads();
    if (tid < 32) {
        float t = red[tid];
        #pragma unroll
        for (int o = 16; o; o >>= 1) t += __shfl_xor_sync(0xffffffffu, t, o);
        if (tid == 0) bc = 1.f / t;
    }
    __syncthreads();
    float inv = bc;
    float* ob = out + (size_t)b * TT;
    ob[tid]        = e0 * inv;
    ob[tid + 1024] = e1 * inv;
    ob[tid + 2048] = e2 * inv;
    ob[tid + 3072] = e3 * inv;
}

// ---------------------------------------------------------------------------
extern "C" void kernel_launch(void* const* d_in, const int* in_sizes, int n_in,
                              void* d_out, int out_size) {
    const float* hidden = (const float*)d_in[0];   // [B, H]
    const float* enc    = (const float*)d_in[1];   // [T, B, H]
    const float* attn_w = (const float*)d_in[2];   // [H, 2H]
    const float* attn_b = (const float*)d_in[3];   // [H]
    const float* v      = (const float*)d_in[4];   // [H]
    float* out = (float*)d_out;                    // [B, 1, T]

    cudaFuncSetAttribute(energy_kernel,
                         cudaFuncAttributeMaxDynamicSharedMemorySize, SMEM_ENERGY);

    pre1_kernel<<<(BATCH * HH) / 8, 256>>>(hidden, attn_w, attn_b);
    w2t_kernel<<<HH, HH>>>(attn_w);
    energy_kernel<<<TB / BM, 256, SMEM_ENERGY>>>(enc, v);
    softmax_kernel<<<BATCH, 1024>>>(out);
}

// round 3
// speedup vs baseline: 1.6337x; 1.6337x over previous
#include <cuda_runtime.h>
#include <cuda_bf16.h>
#include <cstdint>

// Problem constants
#define BATCH 32
#define TT    4096
#define HH    256
#define TB    (TT * BATCH)     // 131072 rows of enc

// -------------------- scratch (static device arrays) -----------------------
__device__ float g_pre1[BATCH * HH];            // W1*hidden + bias
__device__ float g_scores[BATCH * TT];          // transposed scores [b][t]
// Pre-split, pre-swizzled B tiles: [chunk 0..3][term hi/lo][256 n][64 k] bf16
__device__ unsigned char g_bpk[4 * 2 * 32768];  // 256KB

// -------------------- helpers ----------------------------------------------
__device__ __forceinline__ uint32_t smem_u32(const void* p) {
    uint32_t a;
    asm("{ .reg .u64 t; cvta.to.shared.u64 t, %1; cvt.u32.u64 %0, t; }" : "=r"(a) : "l"(p));
    return a;
}
__device__ __forceinline__ void cp16(void* smem_dst, const void* gsrc) {
    unsigned s = (unsigned)__cvta_generic_to_shared(smem_dst);
    asm volatile("cp.async.cg.shared.global [%0], [%1], 16;\n" :: "r"(s), "l"(gsrc));
}
#define CP_COMMIT() asm volatile("cp.async.commit_group;\n" ::: "memory")
#define CP_WAIT0()  asm volatile("cp.async.wait_group 0;\n" ::: "memory")

__device__ __forceinline__ uint32_t pack_bf16x2(float x, float y) {
    // mem order [bf16(x), bf16(y)] : low half = x
    uint32_t r;
    asm("cvt.rn.bf16x2.f32 %0, %1, %2;" : "=r"(r) : "f"(y), "f"(x));
    return r;
}
__device__ __forceinline__ void ldsm4(uint32_t* r, uint32_t addr) {
    asm volatile("ldmatrix.sync.aligned.m8n8.x4.shared.b16 {%0,%1,%2,%3}, [%4];"
                 : "=r"(r[0]), "=r"(r[1]), "=r"(r[2]), "=r"(r[3]) : "r"(addr));
}
__device__ __forceinline__ void mma16816(float* c, const uint32_t* a, uint32_t b0, uint32_t b1) {
    asm volatile("mma.sync.aligned.m16n8k16.row.col.f32.bf16.bf16.f32 "
                 "{%0,%1,%2,%3}, {%4,%5,%6,%7}, {%8,%9}, {%0,%1,%2,%3};"
                 : "+f"(c[0]), "+f"(c[1]), "+f"(c[2]), "+f"(c[3])
                 : "r"(a[0]), "r"(a[1]), "r"(a[2]), "r"(a[3]), "r"(b0), "r"(b1));
}

// ---------------------------------------------------------------------------
// Kernel 1: pre1[b,h] = W1[h,:]*hidden[b,:] + bias[h]
// ---------------------------------------------------------------------------
__global__ void pre1_kernel(const float* __restrict__ hidden,
                            const float* __restrict__ attn_w,
                            const float* __restrict__ attn_b) {
    int gw   = (blockIdx.x * blockDim.x + threadIdx.x) >> 5;
    int lane = threadIdx.x & 31;
    int b = gw >> 8, h = gw & 255;
    const float4* hp = (const float4*)(hidden + (size_t)b * HH);
    const float4* wp = (const float4*)(attn_w + (size_t)h * (2 * HH));
    float4 x0 = hp[lane],      w0 = wp[lane];
    float4 x1 = hp[lane + 32], w1 = wp[lane + 32];
    float s = x0.x*w0.x + x0.y*w0.y + x0.z*w0.z + x0.w*w0.w
            + x1.x*w1.x + x1.y*w1.y + x1.z*w1.z + x1.w*w1.w;
    #pragma unroll
    for (int o = 16; o; o >>= 1) s += __shfl_xor_sync(0xffffffffu, s, o);
    if (lane == 0) g_pre1[gw] = s + attn_b[h];
}

// ---------------------------------------------------------------------------
// Kernel 2: split + swizzle B = W2 (attn_w[:, 256:512]) into g_bpk.
// Per (chunk c, term): [n=256 rows][64 k] bf16, 128B/row, 16B XOR swizzle.
//   Bs[n][k] = B[kglob = c*64+k][n] = attn_w[n*512 + 256 + kglob]
// ---------------------------------------------------------------------------
__global__ void bpack_kernel(const float* __restrict__ attn_w) {
    int idx = blockIdx.x * blockDim.x + threadIdx.x;   // 0 .. 65535
    int c = idx >> 14;
    int r = idx & 16383;
    int n = r >> 6;
    int k = r & 63;
    float val = attn_w[(size_t)n * 512 + 256 + c * 64 + k];
    __nv_bfloat16 hi = __float2bfloat16(val);
    float hif = __bfloat162float(hi);
    __nv_bfloat16 lo = __float2bfloat16(val - hif);
    uint32_t o  = (uint32_t)(k * 2) ^ ((uint32_t)(n & 7) * 16);
    uint32_t so = (uint32_t)n * 128 + o;
    *(uint16_t*)(g_bpk + (c * 2 + 0) * 32768 + so) = *(uint16_t*)&hi;
    *(uint16_t*)(g_bpk + (c * 2 + 1) * 32768 + so) = *(uint16_t*)&lo;
}

// ---------------------------------------------------------------------------
// Kernel 3: split-bf16 HMMA GEMM + fused epilogue.
// CTA: 128 rows x 256 cols, 512 thr (16 warps, 4x4), warp tile 32x64.
// K = 4 real chunks of 64; per chunk 3 terms: ah*bh, ah*bl, al*bh.
// SMEM: As [2 buf][2 term][128][64] bf16 = 64KB @ 0
//       Bs [2 buf][2 term][256][64] bf16 = 128KB @ 65536
// ---------------------------------------------------------------------------
#define SMEM_DYN 196608

__global__ __launch_bounds__(512, 1)
void energy_kernel(const float* __restrict__ enc, const float* __restrict__ v) {
    extern __shared__ __align__(1024) unsigned char smem[];
    const uint32_t sb = smem_u32(smem);
    const int tid = threadIdx.x, wid = tid >> 5, L = tid & 31;
    const int wm = wid >> 2, wn = wid & 3;
    const int r0 = blockIdx.x * 128;

    float acc[2][8][4];
    #pragma unroll
    for (int i = 0; i < 2; i++)
        #pragma unroll
        for (int j = 0; j < 8; j++)
            #pragma unroll
            for (int q = 0; q < 4; q++) acc[i][j][q] = 0.f;

    // ---- per-thread fill indices (A conversion path) ----
    const int frow = tid >> 3;                 // 0..63  (it adds +64)
    const int fc16 = tid & 7;                  // 16B chunk within 128B row
    float4 a_st[2][2];

    auto ldg_A = [&](int c) {
        #pragma unroll
        for (int it = 0; it < 2; it++) {
            int row = frow + it * 64;
            const float4* p = (const float4*)(enc + (size_t)(r0 + row) * HH + c * 64 + fc16 * 8);
            a_st[it][0] = p[0];
            a_st[it][1] = p[1];
        }
    };
    auto sts_A = [&](int buf) {
        #pragma unroll
        for (int it = 0; it < 2; it++) {
            int row = frow + it * 64;
            float4 a0 = a_st[it][0], a1 = a_st[it][1];
            uint32_t h0 = pack_bf16x2(a0.x, a0.y);
            uint32_t h1 = pack_bf16x2(a0.z, a0.w);
            uint32_t h2 = pack_bf16x2(a1.x, a1.y);
            uint32_t h3 = pack_bf16x2(a1.z, a1.w);
            float l0 = a0.x - __uint_as_float(h0 << 16);
            float l1 = a0.y - __uint_as_float(h0 & 0xffff0000u);
            float l2 = a0.z - __uint_as_float(h1 << 16);
            float l3 = a0.w - __uint_as_float(h1 & 0xffff0000u);
            float l4 = a1.x - __uint_as_float(h2 << 16);
            float l5 = a1.y - __uint_as_float(h2 & 0xffff0000u);
            float l6 = a1.z - __uint_as_float(h3 << 16);
            float l7 = a1.w - __uint_as_float(h3 & 0xffff0000u);
            uint32_t q0 = pack_bf16x2(l0, l1);
            uint32_t q1 = pack_bf16x2(l2, l3);
            uint32_t q2 = pack_bf16x2(l4, l5);
            uint32_t q3 = pack_bf16x2(l6, l7);
            uint32_t off = (uint32_t)row * 128 + (((uint32_t)fc16 * 16) ^ ((uint32_t)(row & 7) * 16));
            *(uint4*)(smem + buf * 32768 + off)         = make_uint4(h0, h1, h2, h3);
            *(uint4*)(smem + buf * 32768 + 16384 + off) = make_uint4(q0, q1, q2, q3);
        }
    };
    auto cpy_B = [&](int buf, int c) {
        // 64KB (hi+lo contiguous) linear copy
        #pragma unroll
        for (int st = 0; st < 8; st++) {
            int off = (tid + st * 512) * 16;
            cp16(smem + 65536 + buf * 65536 + off, g_bpk + c * 65536 + off);
        }
        CP_COMMIT();
    };

    // ---- ldmatrix per-thread address components ----
    const int lrow16 = L & 15;             // row within 16-row group
    const uint32_t lcol = (uint32_t)(L >> 4) * 16;  // 16B column select

    auto mma_chunk = [&](int buf) {
        #pragma unroll
        for (int t3 = 0; t3 < 3; t3++) {
            // t3=0: ah*bh  t3=1: ah*bl  t3=2: al*bh
            const uint32_t a_base = sb + (uint32_t)buf * 32768 + (t3 == 2 ? 16384u : 0u);
            const uint32_t b_base = sb + 65536u + (uint32_t)buf * 65536 + (t3 == 1 ? 32768u : 0u);
            #pragma unroll
            for (int ks = 0; ks < 4; ks++) {
                const uint32_t kb = (uint32_t)ks * 32;
                uint32_t af[2][4];
                #pragma unroll
                for (int mi = 0; mi < 2; mi++) {
                    int arow = wm * 32 + mi * 16 + lrow16;
                    uint32_t addr = a_base + (uint32_t)arow * 128 +
                                    ((kb + lcol) ^ ((uint32_t)(arow & 7) * 16));
                    ldsm4(af[mi], addr);
                }
                #pragma unroll
                for (int ni2 = 0; ni2 < 4; ni2++) {
                    uint32_t bf[4];
                    int brow = wn * 64 + ni2 * 16 + lrow16;
                    uint32_t addr = b_base + (uint32_t)brow * 128 +
                                    ((kb + lcol) ^ ((uint32_t)(brow & 7) * 16));
                    ldsm4(bf, addr);
                    #pragma unroll
                    for (int mi = 0; mi < 2; mi++) {
                        mma16816(acc[mi][ni2 * 2 + 0], af[mi], bf[0], bf[2]);
                        mma16816(acc[mi][ni2 * 2 + 1], af[mi], bf[1], bf[3]);
                    }
                }
            }
        }
    };

    // ---- pipelined mainloop over 4 real chunks ----
    ldg_A(0);
    cpy_B(0, 0);
    sts_A(0);
    CP_WAIT0();
    __syncthreads();

    #pragma unroll
    for (int c = 0; c < 4; c++) {
        const int buf = c & 1;
        if (c < 3) { ldg_A(c + 1); cpy_B(buf ^ 1, c + 1); }
        mma_chunk(buf);
        if (c < 3) {
            sts_A(buf ^ 1);
            CP_WAIT0();
        }
        __syncthreads();
    }

    // ---- epilogue: +pre1, relu, dot v, reduce, transposed store ----
    float* pre1s = (float*)smem;                   // [32][257] (reuses As)
    float* vs    = (float*)(smem + 32896);         // [256]
    float* ps    = (float*)(smem + 33920);         // [128][4]
    #pragma unroll
    for (int i = 0; i < 16; i++) {
        int idx = tid + i * 512;                   // 0..8191
        int bb = idx >> 8, cc = idx & 255;
        pre1s[bb * 257 + cc] = g_pre1[idx];
    }
    if (tid < 256) vs[tid] = v[tid];
    __syncthreads();

    #pragma unroll
    for (int mi = 0; mi < 2; mi++) {
        #pragma unroll
        for (int p = 0; p < 2; p++) {
            int row = wm * 32 + mi * 16 + (L >> 2) + p * 8;
            int bb  = row & 31;
            float s = 0.f;
            #pragma unroll
            for (int ni = 0; ni < 8; ni++) {
                int n0 = wn * 64 + ni * 8 + (L & 3) * 2;
                float e0 = acc[mi][ni][p * 2 + 0] + pre1s[bb * 257 + n0];
                float e1 = acc[mi][ni][p * 2 + 1] + pre1s[bb * 257 + n0 + 1];
                s += fmaxf(e0, 0.f) * vs[n0] + fmaxf(e1, 0.f) * vs[n0 + 1];
            }
            s += __shfl_xor_sync(0xffffffffu, s, 1);
            s += __shfl_xor_sync(0xffffffffu, s, 2);
            if ((L & 3) == 0) ps[row * 4 + wn] = s;
        }
    }
    __syncthreads();
    if (tid < 128) {
        float tot = ps[tid * 4] + ps[tid * 4 + 1] + ps[tid * 4 + 2] + ps[tid * 4 + 3];
        g_scores[(size_t)(tid & 31) * TT + blockIdx.x * 4 + (tid >> 5)] = tot;
    }
}

// ---------------------------------------------------------------------------
// Kernel 4: softmax over T per batch row.
// ---------------------------------------------------------------------------
__global__ void softmax_kernel(float* __restrict__ out) {
    int b = blockIdx.x, tid = threadIdx.x;
    __shared__ float red[32];
    __shared__ float bc;
    const float* sc = g_scores + (size_t)b * TT;

    float x0 = sc[tid], x1 = sc[tid + 1024], x2 = sc[tid + 2048], x3 = sc[tid + 3072];
    float m = fmaxf(fmaxf(x0, x1), fmaxf(x2, x3));
    #pragma unroll
    for (int o = 16; o; o >>= 1) m = fmaxf(m, __shfl_xor_sync(0xffffffffu, m, o));
    if ((tid & 31) == 0) red[tid >> 5] = m;
    __syncthreads();
    if (tid < 32) {
        float t = red[tid];
        #pragma unroll
        for (int o = 16; o; o >>= 1) t = fmaxf(t, __shfl_xor_sync(0xffffffffu, t, o));
        if (tid == 0) bc = t;
    }
    __syncthreads();
    m = bc;
    float e0 = expf(x0 - m), e1 = expf(x1 - m), e2 = expf(x2 - m), e3 = expf(x3 - m);
    float ssum = e0 + e1 + e2 + e3;
    #pragma unroll
    for (int o = 16; o; o >>= 1) ssum += __shfl_xor_sync(0xffffffffu, ssum, o);
    if ((tid & 31) == 0) red[tid >> 5] = ssum;
    __syncthreads();
    if (tid < 32) {
        float t = red[tid];
        #pragma unroll
        for (int o = 16; o; o >>= 1) t += __shfl_xor_sync(0xffffffffu, t, o);
        if (tid == 0) bc = 1.f / t;
    }
    __syncthreads();
    float inv = bc;
    float* ob = out + (size_t)b * TT;
    ob[tid]        = e0 * inv;
    ob[tid + 1024] = e1 * inv;
    ob[tid + 2048] = e2 * inv;
    ob[tid + 3072] = e3 * inv;
}

// ---------------------------------------------------------------------------
extern "C" void kernel_launch(void* const* d_in, const int* in_sizes, int n_in,
                              void* d_out, int out_size) {
    const float* hidden = (const float*)d_in[0];   // [B, H]
    const float* enc    = (const float*)d_in[1];   // [T, B, H]
    const float* attn_w = (const float*)d_in[2];   // [H, 2H]
    const float* attn_b = (const float*)d_in[3];   // [H]
    const float* v      = (const float*)d_in[4];   // [H]
    float* out = (float*)d_out;                    // [B, 1, T]

    cudaFuncSetAttribute(energy_kernel,
                         cudaFuncAttributeMaxDynamicSharedMemorySize, SMEM_DYN);

    pre1_kernel<<<(BATCH * HH) / 8, 256>>>(hidden, attn_w, attn_b);
    bpack_kernel<<<256, 256>>>(attn_w);
    energy_kernel<<<TB / 128, 512, SMEM_DYN>>>(enc, v);
    softmax_kernel<<<BATCH, 1024>>>(out);
}

// round 4
// speedup vs baseline: 2.7059x; 1.6563x over previous
#include <cuda_runtime.h>
#include <cuda_fp16.h>
#include <cuda_bf16.h>
#include <cstdint>

// Problem constants
#define BATCH 32
#define TT    4096
#define HH    256
#define TB    (TT * BATCH)     // 131072 rows of enc

// -------------------- scratch (static device arrays) -----------------------
__device__ float g_pre1[BATCH * HH];            // W1*hidden + bias
__device__ float g_scores[BATCH * TT];          // transposed scores [b][t]
// Pre-swizzled B tiles (single fp16 term): [chunk 0..3][256 n][64 k] fp16
__device__ unsigned char g_bpk[4 * 32768];      // 128KB

// -------------------- helpers ----------------------------------------------
__device__ __forceinline__ uint32_t smem_u32(const void* p) {
    uint32_t a;
    asm("{ .reg .u64 t; cvta.to.shared.u64 t, %1; cvt.u32.u64 %0, t; }" : "=r"(a) : "l"(p));
    return a;
}
__device__ __forceinline__ void cp16(void* smem_dst, const void* gsrc) {
    unsigned s = (unsigned)__cvta_generic_to_shared(smem_dst);
    asm volatile("cp.async.cg.shared.global [%0], [%1], 16;\n" :: "r"(s), "l"(gsrc));
}
#define CP_COMMIT() asm volatile("cp.async.commit_group;\n" ::: "memory")
#define CP_WAIT0()  asm volatile("cp.async.wait_group 0;\n" ::: "memory")

__device__ __forceinline__ void ldsm4(uint32_t* r, uint32_t addr) {
    asm volatile("ldmatrix.sync.aligned.m8n8.x4.shared.b16 {%0,%1,%2,%3}, [%4];"
                 : "=r"(r[0]), "=r"(r[1]), "=r"(r[2]), "=r"(r[3]) : "r"(addr));
}
__device__ __forceinline__ void mma16816(float* c, const uint32_t* a, uint32_t b0, uint32_t b1) {
    asm volatile("mma.sync.aligned.m16n8k16.row.col.f32.f16.f16.f32 "
                 "{%0,%1,%2,%3}, {%4,%5,%6,%7}, {%8,%9}, {%0,%1,%2,%3};"
                 : "+f"(c[0]), "+f"(c[1]), "+f"(c[2]), "+f"(c[3])
                 : "r"(a[0]), "r"(a[1]), "r"(a[2]), "r"(a[3]), "r"(b0), "r"(b1));
}

// split one float into fp16 hi (bits) and fp16(residual) (bits)
__device__ __forceinline__ void split_f16(float x, uint16_t& h, uint16_t& l) {
    __half hh = __float2half_rn(x);
    float  r  = x - __half2float(hh);
    __half ll = __float2half_rn(r);
    h = __half_as_ushort(hh);
    l = __half_as_ushort(ll);
}

// ---------------------------------------------------------------------------
// Kernel 1: pre1[b,h] = W1[h,:]*hidden[b,:] + bias[h]
// ---------------------------------------------------------------------------
__global__ void pre1_kernel(const float* __restrict__ hidden,
                            const float* __restrict__ attn_w,
                            const float* __restrict__ attn_b) {
    int gw   = (blockIdx.x * blockDim.x + threadIdx.x) >> 5;
    int lane = threadIdx.x & 31;
    int b = gw >> 8, h = gw & 255;
    const float4* hp = (const float4*)(hidden + (size_t)b * HH);
    const float4* wp = (const float4*)(attn_w + (size_t)h * (2 * HH));
    float4 x0 = hp[lane],      w0 = wp[lane];
    float4 x1 = hp[lane + 32], w1 = wp[lane + 32];
    float s = x0.x*w0.x + x0.y*w0.y + x0.z*w0.z + x0.w*w0.w
            + x1.x*w1.x + x1.y*w1.y + x1.z*w1.z + x1.w*w1.w;
    #pragma unroll
    for (int o = 16; o; o >>= 1) s += __shfl_xor_sync(0xffffffffu, s, o);
    if (lane == 0) g_pre1[gw] = s + attn_b[h];
}

// ---------------------------------------------------------------------------
// Kernel 2: swizzle B = W2 (attn_w[:, 256:512]) into g_bpk as fp16.
// Per chunk c: [n=256 rows][64 k] fp16, 128B/row, 16B XOR swizzle.
//   Bs[n][k] = attn_w[n*512 + 256 + c*64 + k]
// ---------------------------------------------------------------------------
__global__ void bpack_kernel(const float* __restrict__ attn_w) {
    int idx = blockIdx.x * blockDim.x + threadIdx.x;   // 0 .. 65535
    int c = idx >> 14;
    int r = idx & 16383;
    int n = r >> 6;
    int k = r & 63;
    float val = attn_w[(size_t)n * 512 + 256 + c * 64 + k];
    __half hv = __float2half_rn(val);
    uint32_t o  = (uint32_t)(k * 2) ^ ((uint32_t)(n & 7) * 16);
    uint32_t so = (uint32_t)n * 128 + o;
    *(uint16_t*)(g_bpk + c * 32768 + so) = __half_as_ushort(hv);
}

// ---------------------------------------------------------------------------
// Kernel 3: split-fp16 HMMA GEMM (2 terms: Ah*B + Al*B) + fused epilogue.
// CTA: 128 rows x 256 cols, 512 thr (16 warps, 4x4), warp tile 32x64.
// K = 4 chunks of 64.
// SMEM: As [2 buf][hi 16KB | lo 16KB] = 64KB @ 0
//       Bs [2 buf][256][64] fp16      = 64KB @ 65536
// ---------------------------------------------------------------------------
#define SMEM_DYN 131072

__global__ __launch_bounds__(512, 1)
void energy_kernel(const float* __restrict__ enc, const float* __restrict__ v) {
    extern __shared__ __align__(1024) unsigned char smem[];
    const uint32_t sb = smem_u32(smem);
    const int tid = threadIdx.x, wid = tid >> 5, L = tid & 31;
    const int wm = wid >> 2, wn = wid & 3;
    const int r0 = blockIdx.x * 128;

    float acc[2][8][4];
    #pragma unroll
    for (int i = 0; i < 2; i++)
        #pragma unroll
        for (int j = 0; j < 8; j++)
            #pragma unroll
            for (int q = 0; q < 4; q++) acc[i][j][q] = 0.f;

    // ---- per-thread fill indices (A conversion path) ----
    const int frow = tid >> 3;                 // 0..63  (+64 second iter)
    const int fc16 = tid & 7;                  // 16B chunk within 128B row
    float4 a_st[2][2];

    auto ldg_A = [&](int c) {
        #pragma unroll
        for (int it = 0; it < 2; it++) {
            int row = frow + it * 64;
            const float4* p = (const float4*)(enc + (size_t)(r0 + row) * HH + c * 64 + fc16 * 8);
            a_st[it][0] = p[0];
            a_st[it][1] = p[1];
        }
    };
    auto sts_A = [&](int buf) {
        #pragma unroll
        for (int it = 0; it < 2; it++) {
            int row = frow + it * 64;
            uint16_t h[8], l[8];
            split_f16(a_st[it][0].x, h[0], l[0]);
            split_f16(a_st[it][0].y, h[1], l[1]);
            split_f16(a_st[it][0].z, h[2], l[2]);
            split_f16(a_st[it][0].w, h[3], l[3]);
            split_f16(a_st[it][1].x, h[4], l[4]);
            split_f16(a_st[it][1].y, h[5], l[5]);
            split_f16(a_st[it][1].z, h[6], l[6]);
            split_f16(a_st[it][1].w, h[7], l[7]);
            uint4 hv = make_uint4((uint32_t)h[0] | ((uint32_t)h[1] << 16),
                                  (uint32_t)h[2] | ((uint32_t)h[3] << 16),
                                  (uint32_t)h[4] | ((uint32_t)h[5] << 16),
                                  (uint32_t)h[6] | ((uint32_t)h[7] << 16));
            uint4 lv = make_uint4((uint32_t)l[0] | ((uint32_t)l[1] << 16),
                                  (uint32_t)l[2] | ((uint32_t)l[3] << 16),
                                  (uint32_t)l[4] | ((uint32_t)l[5] << 16),
                                  (uint32_t)l[6] | ((uint32_t)l[7] << 16));
            uint32_t off = (uint32_t)row * 128 + (((uint32_t)fc16 * 16) ^ ((uint32_t)(row & 7) * 16));
            *(uint4*)(smem + buf * 32768 + off)         = hv;
            *(uint4*)(smem + buf * 32768 + 16384 + off) = lv;
        }
    };
    auto cpy_B = [&](int buf, int c) {
        // 32KB linear copy of pre-swizzled fp16 tile
        #pragma unroll
        for (int st = 0; st < 4; st++) {
            int off = (tid + st * 512) * 16;
            cp16(smem + 65536 + buf * 32768 + off, g_bpk + c * 32768 + off);
        }
        CP_COMMIT();
    };

    // ---- ldmatrix per-thread address components ----
    const int lrow16 = L & 15;
    const uint32_t lcol = (uint32_t)(L >> 4) * 16;

    auto mma_chunk = [&](int buf) {
        const uint32_t aH = sb + (uint32_t)buf * 32768;
        const uint32_t aL = aH + 16384;
        const uint32_t bB = sb + 65536u + (uint32_t)buf * 32768;
        #pragma unroll
        for (int ks = 0; ks < 4; ks++) {
            const uint32_t kb = (uint32_t)ks * 32;
            uint32_t ah[2][4], al[2][4], bf[4][4];
            #pragma unroll
            for (int mi = 0; mi < 2; mi++) {
                int arow = wm * 32 + mi * 16 + lrow16;
                uint32_t aoff = (uint32_t)arow * 128 + ((kb + lcol) ^ ((uint32_t)(arow & 7) * 16));
                ldsm4(ah[mi], aH + aoff);
                ldsm4(al[mi], aL + aoff);
            }
            #pragma unroll
            for (int ni2 = 0; ni2 < 4; ni2++) {
                int brow = wn * 64 + ni2 * 16 + lrow16;
                uint32_t boff = (uint32_t)brow * 128 + ((kb + lcol) ^ ((uint32_t)(brow & 7) * 16));
                ldsm4(bf[ni2], bB + boff);
            }
            // hi pass (8 distinct accumulators before any reuse)
            #pragma unroll
            for (int ni2 = 0; ni2 < 4; ni2++)
                #pragma unroll
                for (int mi = 0; mi < 2; mi++) {
                    mma16816(acc[mi][ni2 * 2 + 0], ah[mi], bf[ni2][0], bf[ni2][2]);
                    mma16816(acc[mi][ni2 * 2 + 1], ah[mi], bf[ni2][1], bf[ni2][3]);
                }
            // lo pass
            #pragma unroll
            for (int ni2 = 0; ni2 < 4; ni2++)
                #pragma unroll
                for (int mi = 0; mi < 2; mi++) {
                    mma16816(acc[mi][ni2 * 2 + 0], al[mi], bf[ni2][0], bf[ni2][2]);
                    mma16816(acc[mi][ni2 * 2 + 1], al[mi], bf[ni2][1], bf[ni2][3]);
                }
        }
    };

    // ---- pipelined mainloop over 4 chunks ----
    ldg_A(0);
    cpy_B(0, 0);
    sts_A(0);
    CP_WAIT0();
    __syncthreads();

    #pragma unroll
    for (int c = 0; c < 4; c++) {
        const int buf = c & 1;
        if (c < 3) { ldg_A(c + 1); cpy_B(buf ^ 1, c + 1); }
        mma_chunk(buf);
        if (c < 3) {
            sts_A(buf ^ 1);
            CP_WAIT0();
        }
        __syncthreads();
    }

    // ---- epilogue: +pre1, relu, dot v, reduce, transposed store ----
    float* pre1s = (float*)smem;                   // [32][257] (reuses As)
    float* vs    = (float*)(smem + 32896);         // [256]
    float* ps    = (float*)(smem + 33920);         // [128][4]
    #pragma unroll
    for (int i = 0; i < 16; i++) {
        int idx = tid + i * 512;                   // 0..8191
        int bb = idx >> 8, cc = idx & 255;
        pre1s[bb * 257 + cc] = g_pre1[idx];
    }
    if (tid < 256) vs[tid] = v[tid];
    __syncthreads();

    #pragma unroll
    for (int mi = 0; mi < 2; mi++) {
        #pragma unroll
        for (int p = 0; p < 2; p++) {
            int row = wm * 32 + mi * 16 + (L >> 2) + p * 8;
            int bb  = row & 31;
            float s = 0.f;
            #pragma unroll
            for (int ni = 0; ni < 8; ni++) {
                int n0 = wn * 64 + ni * 8 + (L & 3) * 2;
                float e0 = acc[mi][ni][p * 2 + 0] + pre1s[bb * 257 + n0];
                float e1 = acc[mi][ni][p * 2 + 1] + pre1s[bb * 257 + n0 + 1];
                s += fmaxf(e0, 0.f) * vs[n0] + fmaxf(e1, 0.f) * vs[n0 + 1];
            }
            s += __shfl_xor_sync(0xffffffffu, s, 1);
            s += __shfl_xor_sync(0xffffffffu, s, 2);
            if ((L & 3) == 0) ps[row * 4 + wn] = s;
        }
    }
    __syncthreads();
    if (tid < 128) {
        float tot = ps[tid * 4] + ps[tid * 4 + 1] + ps[tid * 4 + 2] + ps[tid * 4 + 3];
        g_scores[(size_t)(tid & 31) * TT + blockIdx.x * 4 + (tid >> 5)] = tot;
    }
}

// ---------------------------------------------------------------------------
// Kernel 4: softmax over T per batch row.
// ---------------------------------------------------------------------------
__global__ void softmax_kernel(float* __restrict__ out) {
    int b = blockIdx.x, tid = threadIdx.x;
    __shared__ float red[32];
    __shared__ float bc;
    const float* sc = g_scores + (size_t)b * TT;

    float x0 = sc[tid], x1 = sc[tid + 1024], x2 = sc[tid + 2048], x3 = sc[tid + 3072];
    float m = fmaxf(fmaxf(x0, x1), fmaxf(x2, x3));
    #pragma unroll
    for (int o = 16; o; o >>= 1) m = fmaxf(m, __shfl_xor_sync(0xffffffffu, m, o));
    if ((tid & 31) == 0) red[tid >> 5] = m;
    __syncthreads();
    if (tid < 32) {
        float t = red[tid];
        #pragma unroll
        for (int o = 16; o; o >>= 1) t = fmaxf(t, __shfl_xor_sync(0xffffffffu, t, o));
        if (tid == 0) bc = t;
    }
    __syncthreads();
    m = bc;
    float e0 = expf(x0 - m), e1 = expf(x1 - m), e2 = expf(x2 - m), e3 = expf(x3 - m);
    float ssum = e0 + e1 + e2 + e3;
    #pragma unroll
    for (int o = 16; o; o >>= 1) ssum += __shfl_xor_sync(0xffffffffu, ssum, o);
    if ((tid & 31) == 0) red[tid >> 5] = ssum;
    __syncthreads();
    if (tid < 32) {
        float t = red[tid];
        #pragma unroll
        for (int o = 16; o; o >>= 1) t += __shfl_xor_sync(0xffffffffu, t, o);
        if (tid == 0) bc = 1.f / t;
    }
    __syncthreads();
    float inv = bc;
    float* ob = out + (size_t)b * TT;
    ob[tid]        = e0 * inv;
    ob[tid + 1024] = e1 * inv;
    ob[tid + 2048] = e2 * inv;
    ob[tid + 3072] = e3 * inv;
}

// ---------------------------------------------------------------------------
extern "C" void kernel_launch(void* const* d_in, const int* in_sizes, int n_in,
                              void* d_out, int out_size) {
    const float* hidden = (const float*)d_in[0];   // [B, H]
    const float* enc    = (const float*)d_in[1];   // [T, B, H]
    const float* attn_w = (const float*)d_in[2];   // [H, 2H]
    const float* attn_b = (const float*)d_in[3];   // [H]
    const float* v      = (const float*)d_in[4];   // [H]
    float* out = (float*)d_out;                    // [B, 1, T]

    cudaFuncSetAttribute(energy_kernel,
                         cudaFuncAttributeMaxDynamicSharedMemorySize, SMEM_DYN);

    pre1_kernel<<<(BATCH * HH) / 8, 256>>>(hidden, attn_w, attn_b);
    bpack_kernel<<<256, 256>>>(attn_w);
    energy_kernel<<<TB / 128, 512, SMEM_DYN>>>(enc, v);
    softmax_kernel<<<BATCH, 1024>>>(out);
}

// round 5
// speedup vs baseline: 4.0304x; 1.4895x over previous
#include <cuda_runtime.h>
#include <cuda_fp16.h>
#include <cstdint>

// Problem constants
#define BATCH 32
#define TT    4096
#define HH    256
#define TB    (TT * BATCH)     // 131072 rows of enc

// -------------------- scratch (static device arrays) -----------------------
__device__ float g_pre1[BATCH * HH];            // W1*hidden + bias
__device__ float g_scores[BATCH * TT];          // transposed scores [b][t]
// Pre-swizzled B tiles (fp16): [chunk 0..3][256 n][64 k]
__device__ unsigned char g_bpk[4 * 32768];      // 128KB

// -------------------- helpers ----------------------------------------------
__device__ __forceinline__ uint32_t smem_u32(const void* p) {
    uint32_t a;
    asm("{ .reg .u64 t; cvta.to.shared.u64 t, %1; cvt.u32.u64 %0, t; }" : "=r"(a) : "l"(p));
    return a;
}
__device__ __forceinline__ void cp16(void* smem_dst, const void* gsrc) {
    unsigned s = (unsigned)__cvta_generic_to_shared(smem_dst);
    asm volatile("cp.async.cg.shared.global [%0], [%1], 16;\n" :: "r"(s), "l"(gsrc));
}
#define CP_COMMIT() asm volatile("cp.async.commit_group;\n" ::: "memory")
#define CP_WAIT0()  asm volatile("cp.async.wait_group 0;\n" ::: "memory")

__device__ __forceinline__ uint32_t pack_f16x2(float x, float y) {
    // mem order [f16(x), f16(y)] : low half = x
    uint32_t r;
    asm("cvt.rn.f16x2.f32 %0, %1, %2;" : "=r"(r) : "f"(y), "f"(x));
    return r;
}
__device__ __forceinline__ void ldsm4(uint32_t* r, uint32_t addr) {
    asm volatile("ldmatrix.sync.aligned.m8n8.x4.shared.b16 {%0,%1,%2,%3}, [%4];"
                 : "=r"(r[0]), "=r"(r[1]), "=r"(r[2]), "=r"(r[3]) : "r"(addr));
}
__device__ __forceinline__ void mma16816(float* c, const uint32_t* a, uint32_t b0, uint32_t b1) {
    asm volatile("mma.sync.aligned.m16n8k16.row.col.f32.f16.f16.f32 "
                 "{%0,%1,%2,%3}, {%4,%5,%6,%7}, {%8,%9}, {%0,%1,%2,%3};"
                 : "+f"(c[0]), "+f"(c[1]), "+f"(c[2]), "+f"(c[3])
                 : "r"(a[0]), "r"(a[1]), "r"(a[2]), "r"(a[3]), "r"(b0), "r"(b1));
}

// ---------------------------------------------------------------------------
// Kernel 1: pre1[b,h] = W1[h,:]*hidden[b,:] + bias[h]
// ---------------------------------------------------------------------------
__global__ void pre1_kernel(const float* __restrict__ hidden,
                            const float* __restrict__ attn_w,
                            const float* __restrict__ attn_b) {
    int gw   = (blockIdx.x * blockDim.x + threadIdx.x) >> 5;
    int lane = threadIdx.x & 31;
    int b = gw >> 8, h = gw & 255;
    const float4* hp = (const float4*)(hidden + (size_t)b * HH);
    const float4* wp = (const float4*)(attn_w + (size_t)h * (2 * HH));
    float4 x0 = hp[lane],      w0 = wp[lane];
    float4 x1 = hp[lane + 32], w1 = wp[lane + 32];
    float s = x0.x*w0.x + x0.y*w0.y + x0.z*w0.z + x0.w*w0.w
            + x1.x*w1.x + x1.y*w1.y + x1.z*w1.z + x1.w*w1.w;
    #pragma unroll
    for (int o = 16; o; o >>= 1) s += __shfl_xor_sync(0xffffffffu, s, o);
    if (lane == 0) g_pre1[gw] = s + attn_b[h];
}

// ---------------------------------------------------------------------------
// Kernel 2: swizzle B = W2 (attn_w[:, 256:512]) into g_bpk as fp16.
// Per chunk c: [n=256 rows][64 k] fp16, 128B/row, 16B XOR swizzle.
// ---------------------------------------------------------------------------
__global__ void bpack_kernel(const float* __restrict__ attn_w) {
    int idx = blockIdx.x * blockDim.x + threadIdx.x;   // 0 .. 65535
    int c = idx >> 14;
    int r = idx & 16383;
    int n = r >> 6;
    int k = r & 63;
    float val = attn_w[(size_t)n * 512 + 256 + c * 64 + k];
    __half hv = __float2half_rn(val);
    uint32_t o  = (uint32_t)(k * 2) ^ ((uint32_t)(n & 7) * 16);
    uint32_t so = (uint32_t)n * 128 + o;
    *(uint16_t*)(g_bpk + c * 32768 + so) = __half_as_ushort(hv);
}

// ---------------------------------------------------------------------------
// Kernel 3: single-term fp16 HMMA GEMM + fused epilogue.
// CTA: 128 rows x 256 cols, 512 thr (16 warps, 4x4), warp tile 32x64.
// K = 4 chunks of 64.
// SMEM: As [2 buf][128][64] fp16 = 32KB @ 0
//       Bs [2 buf][256][64] fp16 = 64KB @ 32768
// ---------------------------------------------------------------------------
#define SMEM_DYN 98304

__global__ __launch_bounds__(512, 1)
void energy_kernel(const float* __restrict__ enc, const float* __restrict__ v) {
    extern __shared__ __align__(1024) unsigned char smem[];
    const uint32_t sb = smem_u32(smem);
    const int tid = threadIdx.x, wid = tid >> 5, L = tid & 31;
    const int wm = wid >> 2, wn = wid & 3;
    const int r0 = blockIdx.x * 128;

    float acc[2][8][4];
    #pragma unroll
    for (int i = 0; i < 2; i++)
        #pragma unroll
        for (int j = 0; j < 8; j++)
            #pragma unroll
            for (int q = 0; q < 4; q++) acc[i][j][q] = 0.f;

    // ---- per-thread fill indices (A conversion path) ----
    const int frow = tid >> 3;                 // 0..63  (+64 second iter)
    const int fc16 = tid & 7;                  // 16B chunk within 128B row
    float4 a_st[2][2];

    auto ldg_A = [&](int c) {
        #pragma unroll
        for (int it = 0; it < 2; it++) {
            int row = frow + it * 64;
            const float4* p = (const float4*)(enc + (size_t)(r0 + row) * HH + c * 64 + fc16 * 8);
            a_st[it][0] = p[0];
            a_st[it][1] = p[1];
        }
    };
    auto sts_A = [&](int buf) {
        #pragma unroll
        for (int it = 0; it < 2; it++) {
            int row = frow + it * 64;
            uint4 hv = make_uint4(pack_f16x2(a_st[it][0].x, a_st[it][0].y),
                                  pack_f16x2(a_st[it][0].z, a_st[it][0].w),
                                  pack_f16x2(a_st[it][1].x, a_st[it][1].y),
                                  pack_f16x2(a_st[it][1].z, a_st[it][1].w));
            uint32_t off = (uint32_t)row * 128 + (((uint32_t)fc16 * 16) ^ ((uint32_t)(row & 7) * 16));
            *(uint4*)(smem + buf * 16384 + off) = hv;
        }
    };
    auto cpy_B = [&](int buf, int c) {
        // 32KB linear copy of pre-swizzled fp16 tile
        #pragma unroll
        for (int st = 0; st < 4; st++) {
            int off = (tid + st * 512) * 16;
            cp16(smem + 32768 + buf * 32768 + off, g_bpk + c * 32768 + off);
        }
        CP_COMMIT();
    };

    // ---- ldmatrix per-thread address components ----
    const int lrow16 = L & 15;
    const uint32_t lcol = (uint32_t)(L >> 4) * 16;

    auto mma_chunk = [&](int buf) {
        const uint32_t aB = sb + (uint32_t)buf * 16384;
        const uint32_t bB = sb + 32768u + (uint32_t)buf * 32768;
        #pragma unroll
        for (int ks = 0; ks < 4; ks++) {
            const uint32_t kb = (uint32_t)ks * 32;
            uint32_t ah[2][4], bf[4][4];
            #pragma unroll
            for (int mi = 0; mi < 2; mi++) {
                int arow = wm * 32 + mi * 16 + lrow16;
                uint32_t aoff = (uint32_t)arow * 128 + ((kb + lcol) ^ ((uint32_t)(arow & 7) * 16));
                ldsm4(ah[mi], aB + aoff);
            }
            #pragma unroll
            for (int ni2 = 0; ni2 < 4; ni2++) {
                int brow = wn * 64 + ni2 * 16 + lrow16;
                uint32_t boff = (uint32_t)brow * 128 + ((kb + lcol) ^ ((uint32_t)(brow & 7) * 16));
                ldsm4(bf[ni2], bB + boff);
            }
            #pragma unroll
            for (int ni2 = 0; ni2 < 4; ni2++)
                #pragma unroll
                for (int mi = 0; mi < 2; mi++) {
                    mma16816(acc[mi][ni2 * 2 + 0], ah[mi], bf[ni2][0], bf[ni2][2]);
                    mma16816(acc[mi][ni2 * 2 + 1], ah[mi], bf[ni2][1], bf[ni2][3]);
                }
        }
    };

    // ---- pipelined mainloop over 4 chunks ----
    ldg_A(0);
    cpy_B(0, 0);
    sts_A(0);
    CP_WAIT0();
    __syncthreads();

    #pragma unroll
    for (int c = 0; c < 4; c++) {
        const int buf = c & 1;
        if (c < 3) { ldg_A(c + 1); cpy_B(buf ^ 1, c + 1); }
        mma_chunk(buf);
        if (c < 3) {
            sts_A(buf ^ 1);
            CP_WAIT0();
        }
        __syncthreads();
    }

    // ---- epilogue: +pre1, relu, dot v, reduce, transposed store ----
    float* pre1s = (float*)smem;                   // [32][257]
    float* vs    = (float*)(smem + 32896);         // [256]
    float* ps    = (float*)(smem + 33920);         // [128][4]
    #pragma unroll
    for (int i = 0; i < 16; i++) {
        int idx = tid + i * 512;                   // 0..8191
        int bb = idx >> 8, cc = idx & 255;
        pre1s[bb * 257 + cc] = g_pre1[idx];
    }
    if (tid < 256) vs[tid] = v[tid];
    __syncthreads();

    #pragma unroll
    for (int mi = 0; mi < 2; mi++) {
        #pragma unroll
        for (int p = 0; p < 2; p++) {
            int row = wm * 32 + mi * 16 + (L >> 2) + p * 8;
            int bb  = row & 31;
            float s = 0.f;
            #pragma unroll
            for (int ni = 0; ni < 8; ni++) {
                int n0 = wn * 64 + ni * 8 + (L & 3) * 2;
                float e0 = acc[mi][ni][p * 2 + 0] + pre1s[bb * 257 + n0];
                float e1 = acc[mi][ni][p * 2 + 1] + pre1s[bb * 257 + n0 + 1];
                s += fmaxf(e0, 0.f) * vs[n0] + fmaxf(e1, 0.f) * vs[n0 + 1];
            }
            s += __shfl_xor_sync(0xffffffffu, s, 1);
            s += __shfl_xor_sync(0xffffffffu, s, 2);
            if ((L & 3) == 0) ps[row * 4 + wn] = s;
        }
    }
    __syncthreads();
    if (tid < 128) {
        float tot = ps[tid * 4] + ps[tid * 4 + 1] + ps[tid * 4 + 2] + ps[tid * 4 + 3];
        g_scores[(size_t)(tid & 31) * TT + blockIdx.x * 4 + (tid >> 5)] = tot;
    }
}

// ---------------------------------------------------------------------------
// Kernel 4: softmax over T per batch row.
// ---------------------------------------------------------------------------
__global__ void softmax_kernel(float* __restrict__ out) {
    int b = blockIdx.x, tid = threadIdx.x;
    __shared__ float red[32];
    __shared__ float bc;
    const float* sc = g_scores + (size_t)b * TT;

    float x0 = sc[tid], x1 = sc[tid + 1024], x2 = sc[tid + 2048], x3 = sc[tid + 3072];
    float m = fmaxf(fmaxf(x0, x1), fmaxf(x2, x3));
    #pragma unroll
    for (int o = 16; o; o >>= 1) m = fmaxf(m, __shfl_xor_sync(0xffffffffu, m, o));
    if ((tid & 31) == 0) red[tid >> 5] = m;
    __syncthreads();
    if (tid < 32) {
        float t = red[tid];
        #pragma unroll
        for (int o = 16; o; o >>= 1) t = fmaxf(t, __shfl_xor_sync(0xffffffffu, t, o));
        if (tid == 0) bc = t;
    }
    __syncthreads();
    m = bc;
    float e0 = expf(x0 - m), e1 = expf(x1 - m), e2 = expf(x2 - m), e3 = expf(x3 - m);
    float ssum = e0 + e1 + e2 + e3;
    #pragma unroll
    for (int o = 16; o; o >>= 1) ssum += __shfl_xor_sync(0xffffffffu, ssum, o);
    if ((tid & 31) == 0) red[tid >> 5] = ssum;
    __syncthreads();
    if (tid < 32) {
        float t = red[tid];
        #pragma unroll
        for (int o = 16; o; o >>= 1) t += __shfl_xor_sync(0xffffffffu, t, o);
        if (tid == 0) bc = 1.f / t;
    }
    __syncthreads();
    float inv = bc;
    float* ob = out + (size_t)b * TT;
    ob[tid]        = e0 * inv;
    ob[tid + 1024] = e1 * inv;
    ob[tid + 2048] = e2 * inv;
    ob[tid + 3072] = e3 * inv;
}

// ---------------------------------------------------------------------------
extern "C" void kernel_launch(void* const* d_in, const int* in_sizes, int n_in,
                              void* d_out, int out_size) {
    const float* hidden = (const float*)d_in[0];   // [B, H]
    const float* enc    = (const float*)d_in[1];   // [T, B, H]
    const float* attn_w = (const float*)d_in[2];   // [H, 2H]
    const float* attn_b = (const float*)d_in[3];   // [H]
    const float* v      = (const float*)d_in[4];   // [H]
    float* out = (float*)d_out;                    // [B, 1, T]

    cudaFuncSetAttribute(energy_kernel,
                         cudaFuncAttributeMaxDynamicSharedMemorySize, SMEM_DYN);

    pre1_kernel<<<(BATCH * HH) / 8, 256>>>(hidden, attn_w, attn_b);
    bpack_kernel<<<256, 256>>>(attn_w);
    energy_kernel<<<TB / 128, 512, SMEM_DYN>>>(enc, v);
    softmax_kernel<<<BATCH, 1024>>>(out);
}

// round 6
// speedup vs baseline: 4.2168x; 1.0462x over previous
#include <cuda_runtime.h>
#include <cuda_fp16.h>
#include <cstdint>

// Problem constants
#define BATCH 32
#define TT    4096
#define HH    256
#define TB    (TT * BATCH)     // 131072 rows of enc

// -------------------- scratch (static device arrays) -----------------------
__device__ float g_pre1[BATCH * HH];            // W1*hidden + bias
__device__ float g_scores[BATCH * TT];          // transposed scores [b][t]
// Pre-swizzled B tiles (fp16): [chunk 0..3][256 n][64 k]
__device__ unsigned char g_bpk[4 * 32768];      // 128KB

// -------------------- helpers ----------------------------------------------
__device__ __forceinline__ uint32_t smem_u32(const void* p) {
    uint32_t a;
    asm("{ .reg .u64 t; cvta.to.shared.u64 t, %1; cvt.u32.u64 %0, t; }" : "=r"(a) : "l"(p));
    return a;
}
__device__ __forceinline__ void cp16(void* smem_dst, const void* gsrc) {
    unsigned s = (unsigned)__cvta_generic_to_shared(smem_dst);
    asm volatile("cp.async.cg.shared.global [%0], [%1], 16;\n" :: "r"(s), "l"(gsrc));
}
#define CP_COMMIT() asm volatile("cp.async.commit_group;\n" ::: "memory")
#define CP_WAIT0()  asm volatile("cp.async.wait_group 0;\n" ::: "memory")

__device__ __forceinline__ uint32_t pack_f16x2(float x, float y) {
    // mem order [f16(x), f16(y)] : low half = x
    uint32_t r;
    asm("cvt.rn.f16x2.f32 %0, %1, %2;" : "=r"(r) : "f"(y), "f"(x));
    return r;
}
__device__ __forceinline__ void ldsm4(uint32_t* r, uint32_t addr) {
    asm volatile("ldmatrix.sync.aligned.m8n8.x4.shared.b16 {%0,%1,%2,%3}, [%4];"
                 : "=r"(r[0]), "=r"(r[1]), "=r"(r[2]), "=r"(r[3]) : "r"(addr));
}
__device__ __forceinline__ void mma16816(float* c, const uint32_t* a, uint32_t b0, uint32_t b1) {
    asm volatile("mma.sync.aligned.m16n8k16.row.col.f32.f16.f16.f32 "
                 "{%0,%1,%2,%3}, {%4,%5,%6,%7}, {%8,%9}, {%0,%1,%2,%3};"
                 : "+f"(c[0]), "+f"(c[1]), "+f"(c[2]), "+f"(c[3])
                 : "r"(a[0]), "r"(a[1]), "r"(a[2]), "r"(a[3]), "r"(b0), "r"(b1));
}

// ---------------------------------------------------------------------------
// Kernel 1 (fused init): blocks [0,1024) do pre1, blocks [1024,1280) do bpack.
//   pre1[b,h] = W1[h,:]*hidden[b,:] + bias[h]
//   bpack: B = W2 (attn_w[:, 256:512]) -> g_bpk fp16, 128B/row, 16B XOR swizzle
// ---------------------------------------------------------------------------
__global__ void init_kernel(const float* __restrict__ hidden,
                            const float* __restrict__ attn_w,
                            const float* __restrict__ attn_b) {
    if (blockIdx.x < 1024) {
        int gw   = (blockIdx.x * 256 + threadIdx.x) >> 5;   // 0..8191
        int lane = threadIdx.x & 31;
        int b = gw >> 8, h = gw & 255;
        const float4* hp = (const float4*)(hidden + (size_t)b * HH);
        const float4* wp = (const float4*)(attn_w + (size_t)h * (2 * HH));
        float4 x0 = hp[lane],      w0 = wp[lane];
        float4 x1 = hp[lane + 32], w1 = wp[lane + 32];
        float s = x0.x*w0.x + x0.y*w0.y + x0.z*w0.z + x0.w*w0.w
                + x1.x*w1.x + x1.y*w1.y + x1.z*w1.z + x1.w*w1.w;
        #pragma unroll
        for (int o = 16; o; o >>= 1) s += __shfl_xor_sync(0xffffffffu, s, o);
        if (lane == 0) g_pre1[gw] = s + attn_b[h];
    } else {
        int idx = (blockIdx.x - 1024) * 256 + threadIdx.x;  // 0..65535
        int c = idx >> 14;
        int r = idx & 16383;
        int n = r >> 6;
        int k = r & 63;
        float val = attn_w[(size_t)n * 512 + 256 + c * 64 + k];
        __half hv = __float2half_rn(val);
        uint32_t o  = (uint32_t)(k * 2) ^ ((uint32_t)(n & 7) * 16);
        uint32_t so = (uint32_t)n * 128 + o;
        *(uint16_t*)(g_bpk + c * 32768 + so) = __half_as_ushort(hv);
    }
}

// ---------------------------------------------------------------------------
// Kernel 2: single-term fp16 HMMA GEMM + fused epilogue. Occupancy 2.
// CTA: 64 rows x 256 cols, 256 thr (8 warps, wm 2 x wn 4), warp tile 32x64.
// K = 4 chunks of 64.
// SMEM: As [2 buf][64][64] fp16  = 16KB @ 0
//       Bs [2 buf][256][64] fp16 = 64KB @ 16384      (80KB total)
// ---------------------------------------------------------------------------
#define SMEM_DYN 81920

__global__ __launch_bounds__(256, 2)
void energy_kernel(const float* __restrict__ enc, const float* __restrict__ v) {
    extern __shared__ __align__(1024) unsigned char smem[];
    const uint32_t sb = smem_u32(smem);
    const int tid = threadIdx.x, wid = tid >> 5, L = tid & 31;
    const int wm = wid >> 2, wn = wid & 3;
    const int r0 = blockIdx.x * 64;

    float acc[2][8][4];
    #pragma unroll
    for (int i = 0; i < 2; i++)
        #pragma unroll
        for (int j = 0; j < 8; j++)
            #pragma unroll
            for (int q = 0; q < 4; q++) acc[i][j][q] = 0.f;

    // ---- per-thread fill indices (A conversion path) ----
    // 64 rows x 64 k fp32: 512 chunks of 8 floats; 2 per thread
    const int frow = tid >> 2;                 // 0..63  (+? no: idx math below)
    const int fc8  = tid & 3;                  // which 8-float chunk (of 8 per row? no 8 chunks/row)
    float4 a_st[2][2];

    auto ldg_A = [&](int c) {
        #pragma unroll
        for (int it = 0; it < 2; it++) {
            int idx = tid + it * 256;          // 0..511
            int row = idx >> 3, c8 = idx & 7;
            const float4* p = (const float4*)(enc + (size_t)(r0 + row) * HH + c * 64 + c8 * 8);
            a_st[it][0] = p[0];
            a_st[it][1] = p[1];
        }
    };
    auto sts_A = [&](int buf) {
        #pragma unroll
        for (int it = 0; it < 2; it++) {
            int idx = tid + it * 256;
            int row = idx >> 3, c8 = idx & 7;
            uint4 hv = make_uint4(pack_f16x2(a_st[it][0].x, a_st[it][0].y),
                                  pack_f16x2(a_st[it][0].z, a_st[it][0].w),
                                  pack_f16x2(a_st[it][1].x, a_st[it][1].y),
                                  pack_f16x2(a_st[it][1].z, a_st[it][1].w));
            uint32_t off = (uint32_t)row * 128 + (((uint32_t)c8 * 16) ^ ((uint32_t)(row & 7) * 16));
            *(uint4*)(smem + buf * 8192 + off) = hv;
        }
    };
    auto cpy_B = [&](int buf, int c) {
        // 32KB linear copy of pre-swizzled fp16 tile; 2048 x 16B, 8 per thread
        #pragma unroll
        for (int st = 0; st < 8; st++) {
            int off = (tid + st * 256) * 16;
            cp16(smem + 16384 + buf * 32768 + off, g_bpk + c * 32768 + off);
        }
        CP_COMMIT();
    };

    // ---- ldmatrix per-thread address components ----
    const int lrow16 = L & 15;
    const uint32_t lcol = (uint32_t)(L >> 4) * 16;

    auto mma_chunk = [&](int buf) {
        const uint32_t aB = sb + (uint32_t)buf * 8192;
        const uint32_t bB = sb + 16384u + (uint32_t)buf * 32768;
        #pragma unroll
        for (int ks = 0; ks < 4; ks++) {
            const uint32_t kb = (uint32_t)ks * 32;
            uint32_t ah[2][4], bf[4][4];
            #pragma unroll
            for (int mi = 0; mi < 2; mi++) {
                int arow = wm * 32 + mi * 16 + lrow16;
                uint32_t aoff = (uint32_t)arow * 128 + ((kb + lcol) ^ ((uint32_t)(arow & 7) * 16));
                ldsm4(ah[mi], aB + aoff);
            }
            #pragma unroll
            for (int ni2 = 0; ni2 < 4; ni2++) {
                int brow = wn * 64 + ni2 * 16 + lrow16;
                uint32_t boff = (uint32_t)brow * 128 + ((kb + lcol) ^ ((uint32_t)(brow & 7) * 16));
                ldsm4(bf[ni2], bB + boff);
            }
            #pragma unroll
            for (int ni2 = 0; ni2 < 4; ni2++)
                #pragma unroll
                for (int mi = 0; mi < 2; mi++) {
                    mma16816(acc[mi][ni2 * 2 + 0], ah[mi], bf[ni2][0], bf[ni2][2]);
                    mma16816(acc[mi][ni2 * 2 + 1], ah[mi], bf[ni2][1], bf[ni2][3]);
                }
        }
    };

    // ---- pipelined mainloop over 4 chunks ----
    ldg_A(0);
    cpy_B(0, 0);
    sts_A(0);
    CP_WAIT0();
    __syncthreads();

    #pragma unroll
    for (int c = 0; c < 4; c++) {
        const int buf = c & 1;
        if (c < 3) { ldg_A(c + 1); cpy_B(buf ^ 1, c + 1); }
        mma_chunk(buf);
        if (c < 3) {
            sts_A(buf ^ 1);
            CP_WAIT0();
        }
        __syncthreads();
    }

    // ---- epilogue: +pre1, relu, dot v, reduce, transposed store ----
    float* pre1s = (float*)smem;                   // [32][257] = 32896B
    float* vs    = (float*)(smem + 32896);         // [256]
    float* ps    = (float*)(smem + 33920);         // [64][4]
    #pragma unroll
    for (int i = 0; i < 32; i++) {
        int idx = tid + i * 256;                   // 0..8191
        int bb = idx >> 8, cc = idx & 255;
        pre1s[bb * 257 + cc] = g_pre1[idx];
    }
    vs[tid] = v[tid];
    __syncthreads();

    #pragma unroll
    for (int mi = 0; mi < 2; mi++) {
        #pragma unroll
        for (int p = 0; p < 2; p++) {
            int row = wm * 32 + mi * 16 + (L >> 2) + p * 8;   // 0..63
            int bb  = row & 31;                    // r0 multiple of 64 -> ok
            float s = 0.f;
            #pragma unroll
            for (int ni = 0; ni < 8; ni++) {
                int n0 = wn * 64 + ni * 8 + (L & 3) * 2;
                float e0 = acc[mi][ni][p * 2 + 0] + pre1s[bb * 257 + n0];
                float e1 = acc[mi][ni][p * 2 + 1] + pre1s[bb * 257 + n0 + 1];
                s += fmaxf(e0, 0.f) * vs[n0] + fmaxf(e1, 0.f) * vs[n0 + 1];
            }
            s += __shfl_xor_sync(0xffffffffu, s, 1);
            s += __shfl_xor_sync(0xffffffffu, s, 2);
            if ((L & 3) == 0) ps[row * 4 + wn] = s;
        }
    }
    __syncthreads();
    if (tid < 64) {
        float tot = ps[tid * 4] + ps[tid * 4 + 1] + ps[tid * 4 + 2] + ps[tid * 4 + 3];
        g_scores[(size_t)(tid & 31) * TT + blockIdx.x * 2 + (tid >> 5)] = tot;
    }
}

// ---------------------------------------------------------------------------
// Kernel 3: softmax over T per batch row (float4 vectorized).
// ---------------------------------------------------------------------------
__global__ void softmax_kernel(float* __restrict__ out) {
    int b = blockIdx.x, tid = threadIdx.x;
    __shared__ float red[32];
    __shared__ float bc;
    const float4* sc4 = (const float4*)(g_scores + (size_t)b * TT);

    float4 x = sc4[tid];
    float m = fmaxf(fmaxf(x.x, x.y), fmaxf(x.z, x.w));
    #pragma unroll
    for (int o = 16; o; o >>= 1) m = fmaxf(m, __shfl_xor_sync(0xffffffffu, m, o));
    if ((tid & 31) == 0) red[tid >> 5] = m;
    __syncthreads();
    if (tid < 32) {
        float t = red[tid];
        #pragma unroll
        for (int o = 16; o; o >>= 1) t = fmaxf(t, __shfl_xor_sync(0xffffffffu, t, o));
        if (tid == 0) bc = t;
    }
    __syncthreads();
    m = bc;
    float e0 = expf(x.x - m), e1 = expf(x.y - m), e2 = expf(x.z - m), e3 = expf(x.w - m);
    float ssum = (e0 + e1) + (e2 + e3);
    #pragma unroll
    for (int o = 16; o; o >>= 1) ssum += __shfl_xor_sync(0xffffffffu, ssum, o);
    if ((tid & 31) == 0) red[tid >> 5] = ssum;
    __syncthreads();
    if (tid < 32) {
        float t = red[tid];
        #pragma unroll
        for (int o = 16; o; o >>= 1) t += __shfl_xor_sync(0xffffffffu, t, o);
        if (tid == 0) bc = 1.f / t;
    }
    __syncthreads();
    float inv = bc;
    float4* ob4 = (float4*)(out + (size_t)b * TT);
    ob4[tid] = make_float4(e0 * inv, e1 * inv, e2 * inv, e3 * inv);
}

// ---------------------------------------------------------------------------
extern "C" void kernel_launch(void* const* d_in, const int* in_sizes, int n_in,
                              void* d_out, int out_size) {
    const float* hidden = (const float*)d_in[0];   // [B, H]
    const float* enc    = (const float*)d_in[1];   // [T, B, H]
    const float* attn_w = (const float*)d_in[2];   // [H, 2H]
    const float* attn_b = (const float*)d_in[3];   // [H]
    const float* v      = (const float*)d_in[4];   // [H]
    float* out = (float*)d_out;                    // [B, 1, T]

    cudaFuncSetAttribute(energy_kernel,
                         cudaFuncAttributeMaxDynamicSharedMemorySize, SMEM_DYN);

    init_kernel<<<1280, 256>>>(hidden, attn_w, attn_b);
    energy_kernel<<<TB / 64, 256, SMEM_DYN>>>(enc, v);
    softmax_kernel<<<BATCH, 1024>>>(out);
}